// round 2
// baseline (speedup 1.0000x reference)
#include <cuda_runtime.h>
#include <cuda_bf16.h>
#include <cstdint>

// Problem constants
#define TT   8192
#define NEXP 8
#define DIMC 1024
#define HIDC 2048

// Tiling
#define BM  128
#define BN  128
#define BK  32
#define BKP 40   // padded smem row stride (bf16 elems) -> conflict-free ldmatrix

// Scratch for the intermediate h = x @ w1^T  (bf16, matches reference's bf16 intermediate)
__device__ __nv_bfloat16 g_hidden[(size_t)TT * HIDC];

static __device__ __forceinline__ uint32_t pack2(float a, float b) {
    __nv_bfloat162 v = __floats2bfloat162_rn(a, b);
    return *reinterpret_cast<uint32_t*>(&v);
}

// Grouped GEMM: C[m, n] = sum_k A[m, k] * B_e[n, k], rows m grouped by expert e.
// A: [TT, K] (fp32 or bf16). Ball: [NEXP, N, K] fp32 weights. C: [TT, N].
// Both GEMM outputs are rounded to bf16 (reference keeps bf16 through both dots).
template <typename AT, typename OT>
__global__ __launch_bounds__(256)
void gemm_grouped(const AT* __restrict__ A, const float* __restrict__ Ball,
                  OT* __restrict__ C, const int* __restrict__ counts,
                  int K, int N) {
    __shared__ __nv_bfloat16 sA[BM][BKP];
    __shared__ __nv_bfloat16 sB[BN][BKP];

    const int tid  = threadIdx.x;
    const int lane = tid & 31;
    const int warp = tid >> 5;
    const int m0 = blockIdx.x * BM;
    const int n0 = blockIdx.y * BN;
    // 8 warps: 2 (m) x 4 (n); warp tile 64x32
    const int wm = (warp >> 2) * 64;
    const int wn = (warp & 3) * 32;

    // global->smem loader mapping: each thread owns 16 contiguous elems of one row
    const int lrow = tid >> 1;
    const int lcol = (tid & 1) * 16;

    int off = 0;
    for (int e = 0; e < NEXP; ++e) {
        const int cnt  = counts[e];
        const int seg0 = off, seg1 = off + cnt;
        off = seg1;
        const int lo = max(seg0, m0), hi = min(seg1, m0 + BM);
        if (lo >= hi) continue;

        const float* B = Ball + (size_t)e * N * K;
        const bool arow_ok = (m0 + lrow >= lo) && (m0 + lrow < hi);

        float acc[4][4][4];
        #pragma unroll
        for (int mi = 0; mi < 4; ++mi)
            #pragma unroll
            for (int ni = 0; ni < 4; ++ni)
                #pragma unroll
                for (int r = 0; r < 4; ++r) acc[mi][ni][r] = 0.f;

        uint32_t ar[8], br[8];  // staged bf16x2 for next tile

        auto load_tiles = [&](int kt) {
            const int k0 = kt * BK + lcol;
            if constexpr (sizeof(AT) == 4) {
                const float4* ap = reinterpret_cast<const float4*>(
                    A + (size_t)(m0 + lrow) * K + k0);
                #pragma unroll
                for (int j = 0; j < 4; ++j) {
                    float4 v = arow_ok ? ap[j] : make_float4(0.f, 0.f, 0.f, 0.f);
                    ar[2 * j]     = pack2(v.x, v.y);
                    ar[2 * j + 1] = pack2(v.z, v.w);
                }
            } else {
                const uint4* ap = reinterpret_cast<const uint4*>(
                    A + (size_t)(m0 + lrow) * K + k0);
                uint4 v0 = arow_ok ? ap[0] : make_uint4(0u, 0u, 0u, 0u);
                uint4 v1 = arow_ok ? ap[1] : make_uint4(0u, 0u, 0u, 0u);
                ar[0] = v0.x; ar[1] = v0.y; ar[2] = v0.z; ar[3] = v0.w;
                ar[4] = v1.x; ar[5] = v1.y; ar[6] = v1.z; ar[7] = v1.w;
            }
            const float4* bp = reinterpret_cast<const float4*>(
                B + (size_t)(n0 + lrow) * K + k0);
            #pragma unroll
            for (int j = 0; j < 4; ++j) {
                float4 v = bp[j];
                br[2 * j]     = pack2(v.x, v.y);
                br[2 * j + 1] = pack2(v.z, v.w);
            }
        };

        load_tiles(0);
        const int KT = K / BK;
        for (int kt = 0; kt < KT; ++kt) {
            // stage -> smem
            {
                uint2* sa = reinterpret_cast<uint2*>(&sA[lrow][lcol]);
                uint2* sb = reinterpret_cast<uint2*>(&sB[lrow][lcol]);
                #pragma unroll
                for (int j = 0; j < 4; ++j) {
                    sa[j] = make_uint2(ar[2 * j], ar[2 * j + 1]);
                    sb[j] = make_uint2(br[2 * j], br[2 * j + 1]);
                }
            }
            __syncthreads();
            if (kt + 1 < KT) load_tiles(kt + 1);  // overlap next gmem loads with compute

            #pragma unroll
            for (int ks = 0; ks < 2; ++ks) {
                const int kk = ks * 16;
                uint32_t a[4][4];
                #pragma unroll
                for (int mi = 0; mi < 4; ++mi) {
                    const void* p = &sA[wm + mi * 16 + (lane & 15)][kk + ((lane >> 4) << 3)];
                    uint32_t addr = (uint32_t)__cvta_generic_to_shared(p);
                    asm volatile(
                        "ldmatrix.sync.aligned.m8n8.x4.shared.b16 {%0,%1,%2,%3}, [%4];"
                        : "=r"(a[mi][0]), "=r"(a[mi][1]), "=r"(a[mi][2]), "=r"(a[mi][3])
                        : "r"(addr));
                }
                uint32_t b[4][2];
                #pragma unroll
                for (int ni = 0; ni < 4; ++ni) {
                    const void* p = &sB[wn + ni * 8 + (lane & 7)][kk + (((lane >> 3) & 1) << 3)];
                    uint32_t addr = (uint32_t)__cvta_generic_to_shared(p);
                    asm volatile(
                        "ldmatrix.sync.aligned.m8n8.x2.shared.b16 {%0,%1}, [%2];"
                        : "=r"(b[ni][0]), "=r"(b[ni][1])
                        : "r"(addr));
                }
                #pragma unroll
                for (int mi = 0; mi < 4; ++mi)
                    #pragma unroll
                    for (int ni = 0; ni < 4; ++ni) {
                        asm volatile(
                            "mma.sync.aligned.m16n8k16.row.col.f32.bf16.bf16.f32 "
                            "{%0,%1,%2,%3}, {%4,%5,%6,%7}, {%8,%9}, {%0,%1,%2,%3};"
                            : "+f"(acc[mi][ni][0]), "+f"(acc[mi][ni][1]),
                              "+f"(acc[mi][ni][2]), "+f"(acc[mi][ni][3])
                            : "r"(a[mi][0]), "r"(a[mi][1]), "r"(a[mi][2]), "r"(a[mi][3]),
                              "r"(b[ni][0]), "r"(b[ni][1]));
                    }
            }
            __syncthreads();
        }

        // Epilogue: bf16-round results (reference keeps bf16 after each dot).
        #pragma unroll
        for (int mi = 0; mi < 4; ++mi) {
            const int r0 = m0 + wm + mi * 16 + (lane >> 2);
            const int r1 = r0 + 8;
            #pragma unroll
            for (int ni = 0; ni < 4; ++ni) {
                const int col = n0 + wn + ni * 8 + (lane & 3) * 2;
                if (r0 >= lo && r0 < hi) {
                    if constexpr (sizeof(OT) == 2) {
                        __nv_bfloat162 v = __floats2bfloat162_rn(acc[mi][ni][0], acc[mi][ni][1]);
                        *reinterpret_cast<__nv_bfloat162*>(C + (size_t)r0 * N + col) = v;
                    } else {
                        float2 v = make_float2(
                            __bfloat162float(__float2bfloat16(acc[mi][ni][0])),
                            __bfloat162float(__float2bfloat16(acc[mi][ni][1])));
                        *reinterpret_cast<float2*>(C + (size_t)r0 * N + col) = v;
                    }
                }
                if (r1 >= lo && r1 < hi) {
                    if constexpr (sizeof(OT) == 2) {
                        __nv_bfloat162 v = __floats2bfloat162_rn(acc[mi][ni][2], acc[mi][ni][3]);
                        *reinterpret_cast<__nv_bfloat162*>(C + (size_t)r1 * N + col) = v;
                    } else {
                        float2 v = make_float2(
                            __bfloat162float(__float2bfloat16(acc[mi][ni][2])),
                            __bfloat162float(__float2bfloat16(acc[mi][ni][3])));
                        *reinterpret_cast<float2*>(C + (size_t)r1 * N + col) = v;
                    }
                }
            }
        }
    }
}

extern "C" void kernel_launch(void* const* d_in, const int* in_sizes, int n_in,
                              void* d_out, int out_size) {
    const float* x      = (const float*)d_in[0];   // [TT, DIMC] fp32
    const float* w1     = (const float*)d_in[1];   // [NEXP, HIDC, DIMC] fp32
    const float* w2     = (const float*)d_in[2];   // [NEXP, DIMC, HIDC] fp32
    const int*   counts = (const int*)d_in[3];     // [NEXP] int32
    float*       out    = (float*)d_out;           // [TT, DIMC] fp32

    __nv_bfloat16* hbuf = nullptr;
    cudaGetSymbolAddress((void**)&hbuf, g_hidden);

    dim3 blk(256);
    // GEMM1: h[T, HID] = x @ w1[e]^T
    gemm_grouped<float, __nv_bfloat16>
        <<<dim3(TT / BM, HIDC / BN), blk>>>(x, w1, hbuf, counts, DIMC, HIDC);
    // GEMM2: out[T, DIM] = h @ w2[e]^T
    gemm_grouped<__nv_bfloat16, float>
        <<<dim3(TT / BM, DIMC / BN), blk>>>(hbuf, w2, out, counts, HIDC, DIMC);
}

// round 5
// speedup vs baseline: 1.8265x; 1.8265x over previous
#include <cuda_runtime.h>
#include <cuda_bf16.h>
#include <cstdint>

// Problem constants
#define TT   8192
#define NEXP 8
#define DIMC 1024
#define HIDC 2048

// Tiling
#define BM      128
#define BN      128
#define BK      64
#define ROWB    144      // padded row stride in bytes (72 bf16) -> conflict-free
#define STAGES  3

static constexpr int A_BYTES     = BM * ROWB;          // 18432
static constexpr int B_BYTES     = BN * ROWB;          // 18432
static constexpr int STAGE_BYTES = A_BYTES + B_BYTES;  // 36864
static constexpr int SMEM_DYN    = STAGES * STAGE_BYTES;  // 110592

// bf16 staging + intermediate
__device__ __nv_bfloat16 g_xb[(size_t)TT * DIMC];
__device__ __nv_bfloat16 g_w1b[(size_t)NEXP * HIDC * DIMC];
__device__ __nv_bfloat16 g_w2b[(size_t)NEXP * DIMC * HIDC];
__device__ __nv_bfloat16 g_hidden[(size_t)TT * HIDC];

static __device__ __forceinline__ uint32_t smem_u32(const void* p) {
    return (uint32_t)__cvta_generic_to_shared(p);
}
static __device__ __forceinline__ void cp16(uint32_t dst, const void* src) {
    asm volatile("cp.async.cg.shared.global [%0], [%1], 16;" :: "r"(dst), "l"(src));
}
static __device__ __forceinline__ void cp_commit() {
    asm volatile("cp.async.commit_group;" ::: "memory");
}
template <int N>
static __device__ __forceinline__ void cp_wait() {
    asm volatile("cp.async.wait_group %0;" :: "n"(N) : "memory");
}
static __device__ __forceinline__ void ldsm_x4(uint32_t* r, uint32_t addr) {
    asm volatile("ldmatrix.sync.aligned.m8n8.x4.shared.b16 {%0,%1,%2,%3}, [%4];"
                 : "=r"(r[0]), "=r"(r[1]), "=r"(r[2]), "=r"(r[3]) : "r"(addr));
}

// ---------------- fp32 -> bf16 pre-pass ----------------
__global__ void cvt_f32_bf16(const float4* __restrict__ in, uint2* __restrict__ out, int n4) {
    int i = blockIdx.x * blockDim.x + threadIdx.x;
    if (i < n4) {
        float4 v = in[i];
        __nv_bfloat162 lo = __floats2bfloat162_rn(v.x, v.y);
        __nv_bfloat162 hi = __floats2bfloat162_rn(v.z, v.w);
        out[i] = make_uint2(*reinterpret_cast<uint32_t*>(&lo),
                            *reinterpret_cast<uint32_t*>(&hi));
    }
}

// ---------------- grouped bf16 GEMM (cp.async + mma.sync) ----------------
// C[m,n] = bf16_round( sum_k A[m,k] * B_e[n,k] ), rows m grouped by expert.
template <typename OT>
__global__ void __launch_bounds__(256, 2)
gemm_grouped(const __nv_bfloat16* __restrict__ A, const __nv_bfloat16* __restrict__ Ball,
             OT* __restrict__ C, const int* __restrict__ counts, int K, int N) {
    extern __shared__ char smem[];

    const int tid  = threadIdx.x;
    const int lane = tid & 31;
    const int warp = tid >> 5;
    const int m0 = blockIdx.x * BM;
    const int n0 = blockIdx.y * BN;
    // 8 warps: 2 (m) x 4 (n); warp tile 64x32
    const int wm = (warp >> 2) * 64;
    const int wn = (warp & 3) * 32;

    const int nk = K / BK;

    // ldmatrix fragment addresses (fixed per thread, per-stage base added later)
    const int fr = lane & 15;                 // fragment row within 16
    const int fc = ((lane >> 4) << 3) * 2;    // 0 or 16 bytes (k half)
    const uint32_t sbase = smem_u32(smem);

    int off = 0;
    for (int e = 0; e < NEXP; ++e) {
        const int cnt = counts[e];
        const int s0 = off;
        off += cnt;
        const int lo = max(s0, m0), hi = min(off, m0 + BM);
        if (lo >= hi) continue;

        const __nv_bfloat16* B = Ball + (size_t)e * N * K;

        float acc[4][4][4];
        #pragma unroll
        for (int mi = 0; mi < 4; ++mi)
            #pragma unroll
            for (int ni = 0; ni < 4; ++ni)
                #pragma unroll
                for (int r = 0; r < 4; ++r) acc[mi][ni][r] = 0.f;

        // loader mapping: 1024 16B-chunks per tile, 4 per thread
        auto load_stage = [&](int s, int kt) {
            char* sA = smem + s * STAGE_BYTES;
            char* sB = sA + A_BYTES;
            int c = tid;
            #pragma unroll
            for (int i = 0; i < 4; ++i, c += 256) {
                const int row = c >> 3, cc = c & 7;
                cp16(smem_u32(sA + row * ROWB + cc * 16),
                     A + (size_t)(m0 + row) * K + kt * BK + cc * 8);
            }
            c = tid;
            #pragma unroll
            for (int i = 0; i < 4; ++i, c += 256) {
                const int row = c >> 3, cc = c & 7;
                cp16(smem_u32(sB + row * ROWB + cc * 16),
                     B + (size_t)(n0 + row) * K + kt * BK + cc * 8);
            }
        };

        __syncthreads();   // smem free of previous segment's readers

        // prologue: fill STAGES-1 stages
        #pragma unroll
        for (int s = 0; s < STAGES - 1; ++s) {
            if (s < nk) load_stage(s, s);
            cp_commit();
        }

        for (int kt = 0; kt < nk; ++kt) {
            cp_wait<STAGES - 2>();
            __syncthreads();

            const int nkt = kt + STAGES - 1;
            if (nkt < nk) load_stage(nkt % STAGES, nkt);
            cp_commit();

            const int s = kt % STAGES;
            const uint32_t aS = sbase + s * STAGE_BYTES;
            const uint32_t bS = aS + A_BYTES;

            #pragma unroll
            for (int ks = 0; ks < BK / 16; ++ks) {
                const int kk = ks * 32;  // bytes
                uint32_t a[4][4];
                #pragma unroll
                for (int mi = 0; mi < 4; ++mi)
                    ldsm_x4(a[mi], aS + (wm + mi * 16 + fr) * ROWB + kk + fc);
                uint32_t b[2][4];
                #pragma unroll
                for (int nj = 0; nj < 2; ++nj)
                    ldsm_x4(b[nj], bS + (wn + nj * 16 + fr) * ROWB + kk + fc);
                #pragma unroll
                for (int mi = 0; mi < 4; ++mi)
                    #pragma unroll
                    for (int n8 = 0; n8 < 4; ++n8) {
                        const uint32_t b0 = b[n8 >> 1][n8 & 1];
                        const uint32_t b1 = b[n8 >> 1][(n8 & 1) + 2];
                        asm volatile(
                            "mma.sync.aligned.m16n8k16.row.col.f32.bf16.bf16.f32 "
                            "{%0,%1,%2,%3}, {%4,%5,%6,%7}, {%8,%9}, {%0,%1,%2,%3};"
                            : "+f"(acc[mi][n8][0]), "+f"(acc[mi][n8][1]),
                              "+f"(acc[mi][n8][2]), "+f"(acc[mi][n8][3])
                            : "r"(a[mi][0]), "r"(a[mi][1]), "r"(a[mi][2]), "r"(a[mi][3]),
                              "r"(b0), "r"(b1));
                    }
            }
        }

        // Epilogue: bf16-round (reference keeps bf16 after each dot), mask by segment.
        #pragma unroll
        for (int mi = 0; mi < 4; ++mi) {
            const int r0 = m0 + wm + mi * 16 + (lane >> 2);
            const int r1 = r0 + 8;
            #pragma unroll
            for (int ni = 0; ni < 4; ++ni) {
                const int col = n0 + wn + ni * 8 + (lane & 3) * 2;
                if (r0 >= lo && r0 < hi) {
                    if constexpr (sizeof(OT) == 2) {
                        __nv_bfloat162 v = __floats2bfloat162_rn(acc[mi][ni][0], acc[mi][ni][1]);
                        *reinterpret_cast<__nv_bfloat162*>(C + (size_t)r0 * N + col) = v;
                    } else {
                        float2 v = make_float2(
                            __bfloat162float(__float2bfloat16(acc[mi][ni][0])),
                            __bfloat162float(__float2bfloat16(acc[mi][ni][1])));
                        *reinterpret_cast<float2*>(C + (size_t)r0 * N + col) = v;
                    }
                }
                if (r1 >= lo && r1 < hi) {
                    if constexpr (sizeof(OT) == 2) {
                        __nv_bfloat162 v = __floats2bfloat162_rn(acc[mi][ni][2], acc[mi][ni][3]);
                        *reinterpret_cast<__nv_bfloat162*>(C + (size_t)r1 * N + col) = v;
                    } else {
                        float2 v = make_float2(
                            __bfloat162float(__float2bfloat16(acc[mi][ni][2])),
                            __bfloat162float(__float2bfloat16(acc[mi][ni][3])));
                        *reinterpret_cast<float2*>(C + (size_t)r1 * N + col) = v;
                    }
                }
            }
        }
    }
}

extern "C" void kernel_launch(void* const* d_in, const int* in_sizes, int n_in,
                              void* d_out, int out_size) {
    const float* x      = (const float*)d_in[0];   // [TT, DIMC]
    const float* w1     = (const float*)d_in[1];   // [NEXP, HIDC, DIMC]
    const float* w2     = (const float*)d_in[2];   // [NEXP, DIMC, HIDC]
    const int*   counts = (const int*)d_in[3];     // [NEXP]
    float*       out    = (float*)d_out;           // [TT, DIMC]

    void *xb, *w1b, *w2b, *hb;
    cudaGetSymbolAddress(&xb,  g_xb);
    cudaGetSymbolAddress(&w1b, g_w1b);
    cudaGetSymbolAddress(&w2b, g_w2b);
    cudaGetSymbolAddress(&hb,  g_hidden);

    cudaFuncSetAttribute(gemm_grouped<__nv_bfloat16>,
                         cudaFuncAttributeMaxDynamicSharedMemorySize, SMEM_DYN);
    cudaFuncSetAttribute(gemm_grouped<float>,
                         cudaFuncAttributeMaxDynamicSharedMemorySize, SMEM_DYN);

    // fp32 -> bf16 conversions
    {
        int n4x = TT * DIMC / 4;
        cvt_f32_bf16<<<(n4x + 255) / 256, 256>>>((const float4*)x, (uint2*)xb, n4x);
        int n4w = NEXP * HIDC * DIMC / 4;
        cvt_f32_bf16<<<(n4w + 255) / 256, 256>>>((const float4*)w1, (uint2*)w1b, n4w);
        cvt_f32_bf16<<<(n4w + 255) / 256, 256>>>((const float4*)w2, (uint2*)w2b, n4w);
    }

    // GEMM1: hidden[T, HID] = x_bf16 @ w1[e]^T   (bf16 out)
    gemm_grouped<__nv_bfloat16><<<dim3(TT / BM, HIDC / BN), 256, SMEM_DYN>>>(
        (const __nv_bfloat16*)xb, (const __nv_bfloat16*)w1b,
        (__nv_bfloat16*)hb, counts, DIMC, HIDC);
    // GEMM2: out[T, DIM] = hidden @ w2[e]^T   (bf16-rounded fp32 out)
    gemm_grouped<float><<<dim3(TT / BM, DIMC / BN), 256, SMEM_DYN>>>(
        (const __nv_bfloat16*)hb, (const __nv_bfloat16*)w2b,
        out, counts, HIDC, DIMC);
}